// round 14
// baseline (speedup 1.0000x reference)
#include <cuda_runtime.h>
#include <cuda_fp16.h>
#include <cstdint>

// ---------------- problem constants ----------------
static constexpr int K_DIM   = 1024;
static constexpr int N_DIM   = 3072;       // 3*DIM
static constexpr int M_TOT   = 8 * 4096;   // 32768 rows
static constexpr int POOL_RK = 8;

// GEMM tiling (R8/R11/R13 config: 128x128 CTA, warp 64x32, 8 warps, 2 CTAs/SM)
static constexpr int TM = 128;
static constexpr int TN = 128;
static constexpr int KC = 64;              // fp16 K per chunk
static constexpr int NK = K_DIM / KC;      // 16 chunks
static constexpr int NSTAGE = 3;

// SMEM: padded rows, 64+8 halves = 144 bytes stride
static constexpr int ROW_HALF = KC + 8;                    // 72
static constexpr int ROW_B    = ROW_HALF * 2;              // 144
static constexpr int TILE_B   = TM * ROW_B;                // 18432 per matrix
static constexpr int STAGE_B  = 2 * TILE_B;                // 36864
static constexpr int SM_BIAS  = 0;                         // 128 f32
static constexpr int SM_EPB   = 512;                       // 8*128 f32
static constexpr int SM_STAGE = 4608;
static constexpr int SM_TOTAL = SM_STAGE + NSTAGE * STAGE_B;  // 115200 (x2 = 225 KB/SM)

// cvt_lora dynamic smem: 16 x 1024 f32 transposed A rows
static constexpr int LORA_SMEM = 16 * 1024 * 4;            // 65536

// ---------------- device scratch ----------------
__device__ __half g_xh[(size_t)M_TOT * K_DIM];   // 64 MB
__device__ __half g_wh[(size_t)N_DIM * K_DIM];   //  6 MB
__device__ float  g_T[(size_t)M_TOT * 16];       //  2 MB (0..7 = q, 8..15 = v)

// ---------------- PTX helpers (baseline sm_80+ PTX only) ----------------
__device__ __forceinline__ uint32_t smem_u32(const void* p) {
    return (uint32_t)__cvta_generic_to_shared(p);
}
__device__ __forceinline__ void cp_async16(uint32_t dst, const void* src) {
    asm volatile("cp.async.cg.shared.global [%0], [%1], 16;"
                 :: "r"(dst), "l"(__cvta_generic_to_global(src)));
}
#define CP_COMMIT() asm volatile("cp.async.commit_group;" ::: "memory")
template <int N> __device__ __forceinline__ void cp_wait() {
    asm volatile("cp.async.wait_group %0;" :: "n"(N) : "memory");
}
__device__ __forceinline__ void ldm_x4(uint32_t& r0, uint32_t& r1, uint32_t& r2, uint32_t& r3,
                                       uint32_t addr) {
    asm volatile("ldmatrix.sync.aligned.m8n8.x4.shared.b16 {%0,%1,%2,%3}, [%4];"
                 : "=r"(r0), "=r"(r1), "=r"(r2), "=r"(r3) : "r"(addr));
}
__device__ __forceinline__ void mma16816(float* c, const uint32_t* a, const uint32_t* b) {
    asm volatile(
        "mma.sync.aligned.m16n8k16.row.col.f32.f16.f16.f32 "
        "{%0,%1,%2,%3}, {%4,%5,%6,%7}, {%8,%9}, {%0,%1,%2,%3};"
        : "+f"(c[0]), "+f"(c[1]), "+f"(c[2]), "+f"(c[3])
        : "r"(a[0]), "r"(a[1]), "r"(a[2]), "r"(a[3]), "r"(b[0]), "r"(b[1]));
}

// ---------------- W convert ----------------
__global__ void cvt_w_kernel(const float* __restrict__ src) {
    size_t i = (size_t)blockIdx.x * blockDim.x + threadIdx.x;
    const size_t n4 = (size_t)N_DIM * K_DIM / 4;
    if (i < n4) {
        float4 v = ((const float4*)src)[i];
        ((__half2*)g_wh)[2 * i]     = __floats2half2_rn(v.x, v.y);
        ((__half2*)g_wh)[2 * i + 1] = __floats2half2_rn(v.z, v.w);
    }
}

// ---------------- fused x convert + LoRA T, SMEM-staged A (R11, proven) ----------------
__global__ void cvt_lora_kernel(const float* __restrict__ x,
                                const float* __restrict__ Aq_pool,
                                const float* __restrict__ Av_pool,
                                const int* __restrict__ idx) {
    extern __shared__ float At[];              // [16][1024]
    const int tid  = threadIdx.x;
    const int lid  = tid & 31;
    const int wib  = tid >> 5;                 // warp in block: 0..7
    const int mb0  = blockIdx.x * 32;          // first row of block
    const int i    = idx[mb0 >> 12];
    const float* aq = Aq_pool + (size_t)i * K_DIM * POOL_RK;
    const float* av = Av_pool + (size_t)i * K_DIM * POOL_RK;

#pragma unroll
    for (int it = 0; it < 8; it++) {
        int s = tid + it * 256;                // 0..2047
        int k = s >> 1, h = (s & 1) * 4;
        float4 q4 = *(const float4*)(aq + (size_t)k * 8 + h);
        float4 v4 = *(const float4*)(av + (size_t)k * 8 + h);
        At[(h + 0) * 1024 + k] = q4.x;  At[(h + 1) * 1024 + k] = q4.y;
        At[(h + 2) * 1024 + k] = q4.z;  At[(h + 3) * 1024 + k] = q4.w;
        At[(h + 8) * 1024 + k]  = v4.x; At[(h + 9) * 1024 + k]  = v4.y;
        At[(h + 10) * 1024 + k] = v4.z; At[(h + 11) * 1024 + k] = v4.w;
    }
    __syncthreads();

    const int m0 = mb0 + wib * 4;

    float acc[4][16];
#pragma unroll
    for (int r = 0; r < 4; r++)
#pragma unroll
        for (int j = 0; j < 16; j++) acc[r][j] = 0.f;

    for (int k0 = lid * 4; k0 < K_DIM; k0 += 128) {   // 8 iterations
        float4 xv[4];
#pragma unroll
        for (int r = 0; r < 4; r++) {
            xv[r] = *(const float4*)(x + (size_t)(m0 + r) * K_DIM + k0);
            __half2 h0 = __floats2half2_rn(xv[r].x, xv[r].y);
            __half2 h1 = __floats2half2_rn(xv[r].z, xv[r].w);
            float2 pk;
            pk.x = __uint_as_float(*(const uint32_t*)&h0);
            pk.y = __uint_as_float(*(const uint32_t*)&h1);
            *(float2*)(g_xh + (size_t)(m0 + r) * K_DIM + k0) = pk;
        }
#pragma unroll
        for (int rr = 0; rr < 16; rr++) {
            float4 a4 = *(const float4*)(At + rr * 1024 + k0);   // conflict-free LDS.128
#pragma unroll
            for (int r = 0; r < 4; r++) {
                acc[r][rr] += xv[r].x * a4.x + xv[r].y * a4.y
                            + xv[r].z * a4.z + xv[r].w * a4.w;
            }
        }
    }
#pragma unroll
    for (int r = 0; r < 4; r++) {
#pragma unroll
        for (int j = 0; j < 16; j++) {
            float s = acc[r][j];
            s += __shfl_xor_sync(0xffffffffu, s, 16);
            s += __shfl_xor_sync(0xffffffffu, s, 8);
            s += __shfl_xor_sync(0xffffffffu, s, 4);
            s += __shfl_xor_sync(0xffffffffu, s, 2);
            s += __shfl_xor_sync(0xffffffffu, s, 1);
            acc[r][j] = s;
        }
        if (lid == 0) {
            float4* o = (float4*)(g_T + (size_t)(m0 + r) * 16);
            o[0] = make_float4(acc[r][0],  acc[r][1],  acc[r][2],  acc[r][3]);
            o[1] = make_float4(acc[r][4],  acc[r][5],  acc[r][6],  acc[r][7]);
            o[2] = make_float4(acc[r][8],  acc[r][9],  acc[r][10], acc[r][11]);
            o[3] = make_float4(acc[r][12], acc[r][13], acc[r][14], acc[r][15]);
        }
    }
}

// ---------------- main GEMM ----------------
// Half-chunk loaders: A tile (x rows) and B tile (W rows), each 512 cp.async.
__device__ __forceinline__ void load_half_A(char* stage, int m0, int chunk) {
    const int t = threadIdx.x;
    const int col0 = chunk * KC;
    uint32_t sA = smem_u32(stage);
#pragma unroll
    for (int i = 0; i < 2; i++) {
        int j   = t + i * 256;      // 0..511
        int row = j >> 2;
        int seg = j & 3;
        // two 16B segs per (row, seg-pair): cover segs {seg, seg+4}
        uint32_t off0 = (uint32_t)(row * ROW_B + seg * 16);
        uint32_t off1 = (uint32_t)(row * ROW_B + (seg + 4) * 16);
        cp_async16(sA + off0, g_xh + (size_t)(m0 + row) * K_DIM + col0 + seg * 8);
        cp_async16(sA + off1, g_xh + (size_t)(m0 + row) * K_DIM + col0 + (seg + 4) * 8);
    }
}
__device__ __forceinline__ void load_half_B(char* stage, int n0, int chunk) {
    const int t = threadIdx.x;
    const int col0 = chunk * KC;
    uint32_t sB = smem_u32(stage) + TILE_B;
#pragma unroll
    for (int i = 0; i < 2; i++) {
        int j   = t + i * 256;      // 0..511
        int row = j >> 2;
        int seg = j & 3;
        uint32_t off0 = (uint32_t)(row * ROW_B + seg * 16);
        uint32_t off1 = (uint32_t)(row * ROW_B + (seg + 4) * 16);
        cp_async16(sB + off0, g_wh + (size_t)(n0 + row) * K_DIM + col0 + seg * 8);
        cp_async16(sB + off1, g_wh + (size_t)(n0 + row) * K_DIM + col0 + (seg + 4) * 8);
    }
}

__global__ void __launch_bounds__(256, 2)
gemm_kernel(const float* __restrict__ bias,
            const float* __restrict__ Bq_pool,
            const float* __restrict__ Bv_pool,
            const int* __restrict__ idx,
            float* __restrict__ out) {
    extern __shared__ char smem[];
    const int tid = threadIdx.x;
    const int wid = tid >> 5;
    const int lid = tid & 31;
    const int wm  = wid & 1;       // 2 warps in M  (64 rows each)
    const int wn  = wid >> 1;      // 4 warps in N  (32 cols each)
    const int n0  = blockIdx.x * TN;
    const int m0  = blockIdx.y * TM;
    const int region = blockIdx.x >> 3;   // 0=q, 1=k, 2=v

    const int phase = ((blockIdx.x ^ blockIdx.y) & 1) * 8;
    const int ksoff = (wid >> 2) * 2;

    // ---- epilogue constants ----
    float* sh_bias = (float*)(smem + SM_BIAS);
    float* sh_B    = (float*)(smem + SM_EPB);
    if (tid < 128) sh_bias[tid] = bias[n0 + tid];
    const int pool_i = idx[blockIdx.y >> 5];   // 32 M-tiles (128 rows) per batch
    if (region != 1) {
        const float* Bp = (region == 0) ? (Bq_pool + (size_t)pool_i * POOL_RK * K_DIM)
                                        : (Bv_pool + (size_t)pool_i * POOL_RK * K_DIM);
        int colbase = (region == 0) ? n0 : (n0 - 2048);
#pragma unroll
        for (int e = tid; e < 1024; e += 256) {
            int r = e >> 7, c = e & 127;
            sh_B[e] = Bp[(size_t)r * K_DIM + colbase + c];
        }
    }

    // ---- accumulators ----
    float acc[4][4][4];
#pragma unroll
    for (int i = 0; i < 4; i++)
#pragma unroll
        for (int j = 0; j < 4; j++)
#pragma unroll
            for (int c = 0; c < 4; c++) acc[i][j][c] = 0.f;

    // per-thread ldmatrix source offsets
    const int a_row = (lid & 15);
    const int a_kh  = (lid >> 4) * 8;
    const int b_row = (lid & 7) + ((lid >> 4) << 3);
    const int b_kh  = ((lid >> 3) & 1) * 8;

    // ---- pipeline prologue: 2 chunks in flight, 2 commit groups per chunk ----
    {
        char* s0 = smem + SM_STAGE + 0 * STAGE_B;
        char* s1 = smem + SM_STAGE + 1 * STAGE_B;
        int c0 = (0 + phase) & 15, c1 = (1 + phase) & 15;
        load_half_A(s0, m0, c0); CP_COMMIT();
        load_half_B(s0, n0, c0); CP_COMMIT();
        load_half_A(s1, m0, c1); CP_COMMIT();
        load_half_B(s1, n0, c1); CP_COMMIT();
    }

    // ---- main K loop: one barrier per iteration, split refill ----
    for (int kc = 0; kc < NK; kc++) {
        if (kc == NK - 1) cp_wait<0>(); else cp_wait<2>();
        __syncthreads();
        // All warps are past compute of kc-1 => stage (kc+2)%3 (read at kc-1) is free.

        char* stage = smem + SM_STAGE + (kc % NSTAGE) * STAGE_B;
        char* nstage = smem + SM_STAGE + ((kc + 2) % NSTAGE) * STAGE_B;
        const int kn = kc + 2;
        const int knc = (kn + phase) & 15;
        uint32_t sA = smem_u32(stage);
        uint32_t sB = sA + TILE_B;
#pragma unroll
        for (int ks0 = 0; ks0 < 4; ks0++) {
            const int ks = (ks0 + ksoff) & 3;
            const int k0 = ks * 16;
            // B first (2 LDSM), then A[0] -> MMAs start after 3 LDSMs;
            // remaining A loads interleave with the MMA stream.
            uint32_t b[2][4];
#pragma unroll
            for (int g = 0; g < 2; g++) {
                uint32_t addr = sB + (uint32_t)((wn * 32 + g * 16 + b_row) * ROW_B
                                                + (k0 + b_kh) * 2);
                ldm_x4(b[g][0], b[g][1], b[g][2], b[g][3], addr);
            }
            uint32_t a[4][4];
            {
                uint32_t addr = sA + (uint32_t)((wm * 64 + 0 * 16 + a_row) * ROW_B
                                                + (k0 + a_kh) * 2);
                ldm_x4(a[0][0], a[0][1], a[0][2], a[0][3], addr);
            }
#pragma unroll
            for (int am = 0; am < 4; am++) {
                if (am < 3) {
                    uint32_t addr = sA + (uint32_t)((wm * 64 + (am + 1) * 16 + a_row) * ROW_B
                                                    + (k0 + a_kh) * 2);
                    ldm_x4(a[am + 1][0], a[am + 1][1], a[am + 1][2], a[am + 1][3], addr);
                }
#pragma unroll
                for (int an = 0; an < 4; an++) {
                    uint32_t bb[2] = { b[an >> 1][(an & 1) * 2],
                                       b[an >> 1][(an & 1) * 2 + 1] };
                    mma16816(acc[am][an], a[am], bb);
                }
            }
            // Split deferred refill: A half after ks0==0, B half after ks0==1.
            // Two commit groups per chunk; cp_wait<2> at loop top leaves exactly
            // the next chunk's two groups outstanding.
            if (ks0 == 0 && kn < NK) { load_half_A(nstage, m0, knc); CP_COMMIT(); }
            if (ks0 == 1 && kn < NK) { load_half_B(nstage, n0, knc); CP_COMMIT(); }
        }
    }

    // ---- epilogue: bias + LoRA + store ----
    const bool lora = (region != 1);
    const int tq = lid >> 2;          // 0..7
    const int tr = lid & 3;           // 0..3
#pragma unroll
    for (int am = 0; am < 4; am++) {
#pragma unroll
        for (int h = 0; h < 2; h++) {
            const int lrow = wm * 64 + am * 16 + tq + h * 8;
            const size_t m = (size_t)(m0 + lrow);
            float t[8];
            if (lora) {
                const float* Tp = g_T + m * 16 + (region == 2 ? 8 : 0);
                float4 t0 = *(const float4*)Tp;
                float4 t1 = *(const float4*)(Tp + 4);
                t[0] = t0.x; t[1] = t0.y; t[2] = t0.z; t[3] = t0.w;
                t[4] = t1.x; t[5] = t1.y; t[6] = t1.z; t[7] = t1.w;
            }
#pragma unroll
            for (int an = 0; an < 4; an++) {
                const int lc = wn * 32 + an * 8 + tr * 2;
                float v0 = acc[am][an][h * 2 + 0] + sh_bias[lc];
                float v1 = acc[am][an][h * 2 + 1] + sh_bias[lc + 1];
                if (lora) {
#pragma unroll
                    for (int rr = 0; rr < 8; rr++) {
                        v0 += t[rr] * sh_B[rr * 128 + lc];
                        v1 += t[rr] * sh_B[rr * 128 + lc + 1];
                    }
                }
                *(float2*)(out + m * N_DIM + n0 + lc) = make_float2(v0, v1);
            }
        }
    }
}

// ---------------- launch ----------------
extern "C" void kernel_launch(void* const* d_in, const int* in_sizes, int n_in,
                              void* d_out, int out_size) {
    (void)in_sizes; (void)n_in; (void)out_size;
    const float* x    = (const float*)d_in[0];
    const float* w    = (const float*)d_in[1];
    const float* bias = (const float*)d_in[2];
    const float* Aq   = (const float*)d_in[3];
    const float* Bq   = (const float*)d_in[4];
    const float* Av   = (const float*)d_in[5];
    const float* Bv   = (const float*)d_in[6];
    const int*   idx  = (const int*)d_in[7];
    float* out = (float*)d_out;

    static bool attr_set = false;
    if (!attr_set) {
        cudaFuncSetAttribute(gemm_kernel, cudaFuncAttributeMaxDynamicSharedMemorySize,
                             SM_TOTAL);
        cudaFuncSetAttribute(cvt_lora_kernel, cudaFuncAttributeMaxDynamicSharedMemorySize,
                             LORA_SMEM);
        attr_set = true;
    }

    const size_t w4 = (size_t)N_DIM * K_DIM / 4;
    cvt_w_kernel<<<(unsigned)((w4 + 255) / 256), 256>>>(w);
    cvt_lora_kernel<<<M_TOT / 32, 256, LORA_SMEM>>>(x, Aq, Av, idx);

    dim3 grid(N_DIM / TN, M_TOT / TM, 1);
    gemm_kernel<<<grid, 256, SM_TOTAL>>>(bias, Bq, Bv, idx, out);
}

// round 15
// speedup vs baseline: 1.0834x; 1.0834x over previous
#include <cuda_runtime.h>
#include <cuda_fp16.h>
#include <cstdint>

// ---------------- problem constants ----------------
static constexpr int K_DIM   = 1024;
static constexpr int N_DIM   = 3072;       // 3*DIM
static constexpr int M_TOT   = 8 * 4096;   // 32768 rows
static constexpr int POOL_RK = 8;

// GEMM tiling (R8/R11/R13 config: 128x128 CTA, warp 64x32, 8 warps, 2 CTAs/SM)
static constexpr int TM = 128;
static constexpr int TN = 128;
static constexpr int KC = 64;              // fp16 K per chunk
static constexpr int NK = K_DIM / KC;      // 16 chunks
static constexpr int NSTAGE = 3;

// SMEM: padded rows, 64+8 halves = 144 bytes stride
static constexpr int ROW_HALF = KC + 8;                    // 72
static constexpr int ROW_B    = ROW_HALF * 2;              // 144
static constexpr int TILE_B   = TM * ROW_B;                // 18432 per matrix
static constexpr int STAGE_B  = 2 * TILE_B;                // 36864
static constexpr int SM_BIAS  = 0;                         // 128 f32
static constexpr int SM_EPB   = 512;                       // 8*128 f32
static constexpr int SM_STAGE = 4608;
static constexpr int SM_TOTAL = SM_STAGE + NSTAGE * STAGE_B;  // 115200 (x2 = 225 KB/SM)

// cvt_lora dynamic smem: 16 x 1024 f32 transposed A rows
static constexpr int LORA_SMEM = 16 * 1024 * 4;            // 65536

// ---------------- device scratch ----------------
__device__ __half g_xh[(size_t)M_TOT * K_DIM];   // 64 MB
__device__ __half g_wh[(size_t)N_DIM * K_DIM];   //  6 MB
__device__ float  g_T[(size_t)M_TOT * 16];       //  2 MB (0..7 = q, 8..15 = v)

// ---------------- PTX helpers (baseline sm_80+ PTX only) ----------------
__device__ __forceinline__ uint32_t smem_u32(const void* p) {
    return (uint32_t)__cvta_generic_to_shared(p);
}
__device__ __forceinline__ void cp_async16(uint32_t dst, const void* src) {
    asm volatile("cp.async.cg.shared.global [%0], [%1], 16;"
                 :: "r"(dst), "l"(__cvta_generic_to_global(src)));
}
#define CP_COMMIT() asm volatile("cp.async.commit_group;" ::: "memory")
template <int N> __device__ __forceinline__ void cp_wait() {
    asm volatile("cp.async.wait_group %0;" :: "n"(N) : "memory");
}
__device__ __forceinline__ void ldm_x4(uint32_t& r0, uint32_t& r1, uint32_t& r2, uint32_t& r3,
                                       uint32_t addr) {
    asm volatile("ldmatrix.sync.aligned.m8n8.x4.shared.b16 {%0,%1,%2,%3}, [%4];"
                 : "=r"(r0), "=r"(r1), "=r"(r2), "=r"(r3) : "r"(addr));
}
__device__ __forceinline__ void mma16816(float* c, const uint32_t* a, const uint32_t* b) {
    asm volatile(
        "mma.sync.aligned.m16n8k16.row.col.f32.f16.f16.f32 "
        "{%0,%1,%2,%3}, {%4,%5,%6,%7}, {%8,%9}, {%0,%1,%2,%3};"
        : "+f"(c[0]), "+f"(c[1]), "+f"(c[2]), "+f"(c[3])
        : "r"(a[0]), "r"(a[1]), "r"(a[2]), "r"(a[3]), "r"(b[0]), "r"(b[1]));
}

// ---------------- W convert ----------------
__global__ void cvt_w_kernel(const float* __restrict__ src) {
    size_t i = (size_t)blockIdx.x * blockDim.x + threadIdx.x;
    const size_t n4 = (size_t)N_DIM * K_DIM / 4;
    if (i < n4) {
        float4 v = ((const float4*)src)[i];
        ((__half2*)g_wh)[2 * i]     = __floats2half2_rn(v.x, v.y);
        ((__half2*)g_wh)[2 * i + 1] = __floats2half2_rn(v.z, v.w);
    }
}

// ---------------- fused x convert + LoRA T, SMEM-staged A (R11, proven) ----------------
__global__ void cvt_lora_kernel(const float* __restrict__ x,
                                const float* __restrict__ Aq_pool,
                                const float* __restrict__ Av_pool,
                                const int* __restrict__ idx) {
    extern __shared__ float At[];              // [16][1024]
    const int tid  = threadIdx.x;
    const int lid  = tid & 31;
    const int wib  = tid >> 5;                 // warp in block: 0..7
    const int mb0  = blockIdx.x * 32;          // first row of block
    const int i    = idx[mb0 >> 12];
    const float* aq = Aq_pool + (size_t)i * K_DIM * POOL_RK;
    const float* av = Av_pool + (size_t)i * K_DIM * POOL_RK;

#pragma unroll
    for (int it = 0; it < 8; it++) {
        int s = tid + it * 256;                // 0..2047
        int k = s >> 1, h = (s & 1) * 4;
        float4 q4 = *(const float4*)(aq + (size_t)k * 8 + h);
        float4 v4 = *(const float4*)(av + (size_t)k * 8 + h);
        At[(h + 0) * 1024 + k] = q4.x;  At[(h + 1) * 1024 + k] = q4.y;
        At[(h + 2) * 1024 + k] = q4.z;  At[(h + 3) * 1024 + k] = q4.w;
        At[(h + 8) * 1024 + k]  = v4.x; At[(h + 9) * 1024 + k]  = v4.y;
        At[(h + 10) * 1024 + k] = v4.z; At[(h + 11) * 1024 + k] = v4.w;
    }
    __syncthreads();

    const int m0 = mb0 + wib * 4;

    float acc[4][16];
#pragma unroll
    for (int r = 0; r < 4; r++)
#pragma unroll
        for (int j = 0; j < 16; j++) acc[r][j] = 0.f;

    for (int k0 = lid * 4; k0 < K_DIM; k0 += 128) {   // 8 iterations
        float4 xv[4];
#pragma unroll
        for (int r = 0; r < 4; r++) {
            xv[r] = *(const float4*)(x + (size_t)(m0 + r) * K_DIM + k0);
            __half2 h0 = __floats2half2_rn(xv[r].x, xv[r].y);
            __half2 h1 = __floats2half2_rn(xv[r].z, xv[r].w);
            float2 pk;
            pk.x = __uint_as_float(*(const uint32_t*)&h0);
            pk.y = __uint_as_float(*(const uint32_t*)&h1);
            *(float2*)(g_xh + (size_t)(m0 + r) * K_DIM + k0) = pk;
        }
#pragma unroll
        for (int rr = 0; rr < 16; rr++) {
            float4 a4 = *(const float4*)(At + rr * 1024 + k0);   // conflict-free LDS.128
#pragma unroll
            for (int r = 0; r < 4; r++) {
                acc[r][rr] += xv[r].x * a4.x + xv[r].y * a4.y
                            + xv[r].z * a4.z + xv[r].w * a4.w;
            }
        }
    }
#pragma unroll
    for (int r = 0; r < 4; r++) {
#pragma unroll
        for (int j = 0; j < 16; j++) {
            float s = acc[r][j];
            s += __shfl_xor_sync(0xffffffffu, s, 16);
            s += __shfl_xor_sync(0xffffffffu, s, 8);
            s += __shfl_xor_sync(0xffffffffu, s, 4);
            s += __shfl_xor_sync(0xffffffffu, s, 2);
            s += __shfl_xor_sync(0xffffffffu, s, 1);
            acc[r][j] = s;
        }
        if (lid == 0) {
            float4* o = (float4*)(g_T + (size_t)(m0 + r) * 16);
            o[0] = make_float4(acc[r][0],  acc[r][1],  acc[r][2],  acc[r][3]);
            o[1] = make_float4(acc[r][4],  acc[r][5],  acc[r][6],  acc[r][7]);
            o[2] = make_float4(acc[r][8],  acc[r][9],  acc[r][10], acc[r][11]);
            o[3] = make_float4(acc[r][12], acc[r][13], acc[r][14], acc[r][15]);
        }
    }
}

// ---------------- main GEMM ----------------
// Half of the R13 load_chunk with IDENTICAL per-thread addressing:
// H=0 -> iterations i in {0,1}; H=1 -> iterations i in {2,3}.
template <int H>
__device__ __forceinline__ void load_chunk_half(char* stage, int m0, int n0, int chunk) {
    const int t = threadIdx.x;
    const int col0 = chunk * KC;
    uint32_t sA = smem_u32(stage);
    uint32_t sB = sA + TILE_B;
#pragma unroll
    for (int i = 2 * H; i < 2 * H + 2; i++) {
        int j   = t + i * 256;      // 0..1023 : 16B segments of a 128x64 fp16 tile
        int row = j >> 3;
        int seg = j & 7;
        uint32_t off = (uint32_t)(row * ROW_B + seg * 16);
        cp_async16(sA + off, g_xh + (size_t)(m0 + row) * K_DIM + col0 + seg * 8);
        cp_async16(sB + off, g_wh + (size_t)(n0 + row) * K_DIM + col0 + seg * 8);
    }
}
__device__ __forceinline__ void load_chunk(char* stage, int m0, int n0, int chunk) {
    load_chunk_half<0>(stage, m0, n0, chunk);
    load_chunk_half<1>(stage, m0, n0, chunk);
}

__global__ void __launch_bounds__(256, 2)
gemm_kernel(const float* __restrict__ bias,
            const float* __restrict__ Bq_pool,
            const float* __restrict__ Bv_pool,
            const int* __restrict__ idx,
            float* __restrict__ out) {
    extern __shared__ char smem[];
    const int tid = threadIdx.x;
    const int wid = tid >> 5;
    const int lid = tid & 31;
    const int wm  = wid & 1;       // 2 warps in M  (64 rows each)
    const int wn  = wid >> 1;      // 4 warps in N  (32 cols each)
    const int n0  = blockIdx.x * TN;
    const int m0  = blockIdx.y * TM;
    const int region = blockIdx.x >> 3;   // 0=q, 1=k, 2=v

    const int phase = ((blockIdx.x ^ blockIdx.y) & 1) * 8;
    const int ksoff = (wid >> 2) * 2;

    // ---- epilogue constants ----
    float* sh_bias = (float*)(smem + SM_BIAS);
    float* sh_B    = (float*)(smem + SM_EPB);
    if (tid < 128) sh_bias[tid] = bias[n0 + tid];
    const int pool_i = idx[blockIdx.y >> 5];   // 32 M-tiles (128 rows) per batch
    if (region != 1) {
        const float* Bp = (region == 0) ? (Bq_pool + (size_t)pool_i * POOL_RK * K_DIM)
                                        : (Bv_pool + (size_t)pool_i * POOL_RK * K_DIM);
        int colbase = (region == 0) ? n0 : (n0 - 2048);
#pragma unroll
        for (int e = tid; e < 1024; e += 256) {
            int r = e >> 7, c = e & 127;
            sh_B[e] = Bp[(size_t)r * K_DIM + colbase + c];
        }
    }

    // ---- accumulators ----
    float acc[4][4][4];
#pragma unroll
    for (int i = 0; i < 4; i++)
#pragma unroll
        for (int j = 0; j < 4; j++)
#pragma unroll
            for (int c = 0; c < 4; c++) acc[i][j][c] = 0.f;

    // per-thread ldmatrix source offsets
    const int a_row = (lid & 15);
    const int a_kh  = (lid >> 4) * 8;
    const int b_row = (lid & 7) + ((lid >> 4) << 3);
    const int b_kh  = ((lid >> 3) & 1) * 8;

    // ---- pipeline prologue: 2 stages in flight (one commit group per chunk) ----
    load_chunk(smem + SM_STAGE + 0 * STAGE_B, m0, n0, (0 + phase) & 15); CP_COMMIT();
    load_chunk(smem + SM_STAGE + 1 * STAGE_B, m0, n0, (1 + phase) & 15); CP_COMMIT();

    // ---- main K loop: one barrier per iteration ----
    for (int kc = 0; kc < NK; kc++) {
        if (kc == NK - 1) cp_wait<0>(); else cp_wait<1>();
        __syncthreads();
        // All warps are past compute of kc-1 => stage (kc+2)%3 (read at kc-1) is free.

        char* stage  = smem + SM_STAGE + (kc % NSTAGE) * STAGE_B;
        char* nstage = smem + SM_STAGE + ((kc + 2) % NSTAGE) * STAGE_B;
        const int kn  = kc + 2;
        const int knc = (kn + phase) & 15;
        uint32_t sA = smem_u32(stage);
        uint32_t sB = sA + TILE_B;
#pragma unroll
        for (int ks0 = 0; ks0 < 4; ks0++) {
            const int ks = (ks0 + ksoff) & 3;
            const int k0 = ks * 16;
            // B first (2 LDSM), then A[0] -> MMAs start after 3 LDSMs;
            // remaining A loads interleave with the MMA stream.
            uint32_t b[2][4];
#pragma unroll
            for (int g = 0; g < 2; g++) {
                uint32_t addr = sB + (uint32_t)((wn * 32 + g * 16 + b_row) * ROW_B
                                                + (k0 + b_kh) * 2);
                ldm_x4(b[g][0], b[g][1], b[g][2], b[g][3], addr);
            }
            uint32_t a[4][4];
            {
                uint32_t addr = sA + (uint32_t)((wm * 64 + 0 * 16 + a_row) * ROW_B
                                                + (k0 + a_kh) * 2);
                ldm_x4(a[0][0], a[0][1], a[0][2], a[0][3], addr);
            }
#pragma unroll
            for (int am = 0; am < 4; am++) {
                if (am < 3) {
                    uint32_t addr = sA + (uint32_t)((wm * 64 + (am + 1) * 16 + a_row) * ROW_B
                                                    + (k0 + a_kh) * 2);
                    ldm_x4(a[am + 1][0], a[am + 1][1], a[am + 1][2], a[am + 1][3], addr);
                }
#pragma unroll
                for (int an = 0; an < 4; an++) {
                    uint32_t bb[2] = { b[an >> 1][(an & 1) * 2],
                                       b[an >> 1][(an & 1) * 2 + 1] };
                    mma16816(acc[am][an], a[am], bb);
                }
            }
            // Deferred split refill with R13-identical addressing and commit
            // discipline: first half after ks0==0, second half + single commit
            // after ks0==1. Exactly ONE commit group per chunk -> cp_wait<1>
            // semantics bit-identical to R13; only issue placement changes.
            if (ks0 == 0 && kn < NK) { load_chunk_half<0>(nstage, m0, n0, knc); }
            if (ks0 == 1 && kn < NK) { load_chunk_half<1>(nstage, m0, n0, knc); CP_COMMIT(); }
        }
    }

    // ---- epilogue: bias + LoRA + store ----
    const bool lora = (region != 1);
    const int tq = lid >> 2;          // 0..7
    const int tr = lid & 3;           // 0..3
#pragma unroll
    for (int am = 0; am < 4; am++) {
#pragma unroll
        for (int h = 0; h < 2; h++) {
            const int lrow = wm * 64 + am * 16 + tq + h * 8;
            const size_t m = (size_t)(m0 + lrow);
            float t[8];
            if (lora) {
                const float* Tp = g_T + m * 16 + (region == 2 ? 8 : 0);
                float4 t0 = *(const float4*)Tp;
                float4 t1 = *(const float4*)(Tp + 4);
                t[0] = t0.x; t[1] = t0.y; t[2] = t0.z; t[3] = t0.w;
                t[4] = t1.x; t[5] = t1.y; t[6] = t1.z; t[7] = t1.w;
            }
#pragma unroll
            for (int an = 0; an < 4; an++) {
                const int lc = wn * 32 + an * 8 + tr * 2;
                float v0 = acc[am][an][h * 2 + 0] + sh_bias[lc];
                float v1 = acc[am][an][h * 2 + 1] + sh_bias[lc + 1];
                if (lora) {
#pragma unroll
                    for (int rr = 0; rr < 8; rr++) {
                        v0 += t[rr] * sh_B[rr * 128 + lc];
                        v1 += t[rr] * sh_B[rr * 128 + lc + 1];
                    }
                }
                *(float2*)(out + m * N_DIM + n0 + lc) = make_float2(v0, v1);
            }
        }
    }
}

// ---------------- launch ----------------
extern "C" void kernel_launch(void* const* d_in, const int* in_sizes, int n_in,
                              void* d_out, int out_size) {
    (void)in_sizes; (void)n_in; (void)out_size;
    const float* x    = (const float*)d_in[0];
    const float* w    = (const float*)d_in[1];
    const float* bias = (const float*)d_in[2];
    const float* Aq   = (const float*)d_in[3];
    const float* Bq   = (const float*)d_in[4];
    const float* Av   = (const float*)d_in[5];
    const float* Bv   = (const float*)d_in[6];
    const int*   idx  = (const int*)d_in[7];
    float* out = (float*)d_out;

    static bool attr_set = false;
    if (!attr_set) {
        cudaFuncSetAttribute(gemm_kernel, cudaFuncAttributeMaxDynamicSharedMemorySize,
                             SM_TOTAL);
        cudaFuncSetAttribute(cvt_lora_kernel, cudaFuncAttributeMaxDynamicSharedMemorySize,
                             LORA_SMEM);
        attr_set = true;
    }

    const size_t w4 = (size_t)N_DIM * K_DIM / 4;
    cvt_w_kernel<<<(unsigned)((w4 + 255) / 256), 256>>>(w);
    cvt_lora_kernel<<<M_TOT / 32, 256, LORA_SMEM>>>(x, Aq, Av, idx);

    dim3 grid(N_DIM / TN, M_TOT / TM, 1);
    gemm_kernel<<<grid, 256, SM_TOTAL>>>(bias, Bq, Bv, idx, out);
}

// round 17
// speedup vs baseline: 1.1369x; 1.0494x over previous
#include <cuda_runtime.h>
#include <cuda_fp16.h>
#include <cstdint>

// ---------------- problem constants ----------------
static constexpr int K_DIM   = 1024;
static constexpr int N_DIM   = 3072;       // 3*DIM
static constexpr int M_TOT   = 8 * 4096;   // 32768 rows
static constexpr int POOL_RK = 8;

// GEMM tiling (R13/R15 config: 128x128 CTA, warp 64x32, 8 warps, 2 CTAs/SM)
static constexpr int TM = 128;
static constexpr int TN = 128;
static constexpr int KC = 64;              // fp16 K per chunk
static constexpr int NK = K_DIM / KC;      // 16 chunks
static constexpr int NSTAGE = 3;

// SMEM: padded rows, 64+8 halves = 144 bytes stride
static constexpr int ROW_HALF = KC + 8;                    // 72
static constexpr int ROW_B    = ROW_HALF * 2;              // 144
static constexpr int TILE_B   = TM * ROW_B;                // 18432 per matrix
static constexpr int STAGE_B  = 2 * TILE_B;                // 36864
static constexpr int SM_BIAS  = 0;                         // 128 f32
static constexpr int SM_EPB   = 512;                       // 8*128 f32
static constexpr int SM_STAGE = 4608;
static constexpr int SM_TOTAL = SM_STAGE + NSTAGE * STAGE_B;  // 115200 (x2 = 225 KB/SM)

// cvt_lora dynamic smem: 16 x 1024 f32 transposed A rows
static constexpr int LORA_SMEM = 16 * 1024 * 4;            // 65536

// ---------------- device scratch ----------------
__device__ __half g_xh[(size_t)M_TOT * K_DIM];   // 64 MB
__device__ __half g_wh[(size_t)N_DIM * K_DIM];   //  6 MB
__device__ float  g_T[(size_t)M_TOT * 16];       //  2 MB (0..7 = q, 8..15 = v)

// ---------------- PTX helpers (baseline sm_80+ PTX only) ----------------
__device__ __forceinline__ uint32_t smem_u32(const void* p) {
    return (uint32_t)__cvta_generic_to_shared(p);
}
__device__ __forceinline__ void cp_async16(uint32_t dst, const void* src) {
    asm volatile("cp.async.cg.shared.global [%0], [%1], 16;"
                 :: "r"(dst), "l"(__cvta_generic_to_global(src)));
}
#define CP_COMMIT() asm volatile("cp.async.commit_group;" ::: "memory")
template <int N> __device__ __forceinline__ void cp_wait() {
    asm volatile("cp.async.wait_group %0;" :: "n"(N) : "memory");
}
__device__ __forceinline__ void ldm_x4(uint32_t& r0, uint32_t& r1, uint32_t& r2, uint32_t& r3,
                                       uint32_t addr) {
    asm volatile("ldmatrix.sync.aligned.m8n8.x4.shared.b16 {%0,%1,%2,%3}, [%4];"
                 : "=r"(r0), "=r"(r1), "=r"(r2), "=r"(r3) : "r"(addr));
}
__device__ __forceinline__ void mma16816(float* c, const uint32_t* a, const uint32_t* b) {
    asm volatile(
        "mma.sync.aligned.m16n8k16.row.col.f32.f16.f16.f32 "
        "{%0,%1,%2,%3}, {%4,%5,%6,%7}, {%8,%9}, {%0,%1,%2,%3};"
        : "+f"(c[0]), "+f"(c[1]), "+f"(c[2]), "+f"(c[3])
        : "r"(a[0]), "r"(a[1]), "r"(a[2]), "r"(a[3]), "r"(b[0]), "r"(b[1]));
}

// ---------------- W convert ----------------
__global__ void cvt_w_kernel(const float* __restrict__ src) {
    size_t i = (size_t)blockIdx.x * blockDim.x + threadIdx.x;
    const size_t n4 = (size_t)N_DIM * K_DIM / 4;
    if (i < n4) {
        float4 v = ((const float4*)src)[i];
        ((__half2*)g_wh)[2 * i]     = __floats2half2_rn(v.x, v.y);
        ((__half2*)g_wh)[2 * i + 1] = __floats2half2_rn(v.z, v.w);
    }
}

// ---------------- fused x convert + LoRA T, SMEM-staged A (R11, proven) ----------------
__global__ void cvt_lora_kernel(const float* __restrict__ x,
                                const float* __restrict__ Aq_pool,
                                const float* __restrict__ Av_pool,
                                const int* __restrict__ idx) {
    extern __shared__ float At[];              // [16][1024]
    const int tid  = threadIdx.x;
    const int lid  = tid & 31;
    const int wib  = tid >> 5;                 // warp in block: 0..7
    const int mb0  = blockIdx.x * 32;          // first row of block
    const int i    = idx[mb0 >> 12];
    const float* aq = Aq_pool + (size_t)i * K_DIM * POOL_RK;
    const float* av = Av_pool + (size_t)i * K_DIM * POOL_RK;

#pragma unroll
    for (int it = 0; it < 8; it++) {
        int s = tid + it * 256;                // 0..2047
        int k = s >> 1, h = (s & 1) * 4;
        float4 q4 = *(const float4*)(aq + (size_t)k * 8 + h);
        float4 v4 = *(const float4*)(av + (size_t)k * 8 + h);
        At[(h + 0) * 1024 + k] = q4.x;  At[(h + 1) * 1024 + k] = q4.y;
        At[(h + 2) * 1024 + k] = q4.z;  At[(h + 3) * 1024 + k] = q4.w;
        At[(h + 8) * 1024 + k]  = v4.x; At[(h + 9) * 1024 + k]  = v4.y;
        At[(h + 10) * 1024 + k] = v4.z; At[(h + 11) * 1024 + k] = v4.w;
    }
    __syncthreads();

    const int m0 = mb0 + wib * 4;

    float acc[4][16];
#pragma unroll
    for (int r = 0; r < 4; r++)
#pragma unroll
        for (int j = 0; j < 16; j++) acc[r][j] = 0.f;

    for (int k0 = lid * 4; k0 < K_DIM; k0 += 128) {   // 8 iterations
        float4 xv[4];
#pragma unroll
        for (int r = 0; r < 4; r++) {
            xv[r] = *(const float4*)(x + (size_t)(m0 + r) * K_DIM + k0);
            __half2 h0 = __floats2half2_rn(xv[r].x, xv[r].y);
            __half2 h1 = __floats2half2_rn(xv[r].z, xv[r].w);
            float2 pk;
            pk.x = __uint_as_float(*(const uint32_t*)&h0);
            pk.y = __uint_as_float(*(const uint32_t*)&h1);
            *(float2*)(g_xh + (size_t)(m0 + r) * K_DIM + k0) = pk;
        }
#pragma unroll
        for (int rr = 0; rr < 16; rr++) {
            float4 a4 = *(const float4*)(At + rr * 1024 + k0);   // conflict-free LDS.128
#pragma unroll
            for (int r = 0; r < 4; r++) {
                acc[r][rr] += xv[r].x * a4.x + xv[r].y * a4.y
                            + xv[r].z * a4.z + xv[r].w * a4.w;
            }
        }
    }
#pragma unroll
    for (int r = 0; r < 4; r++) {
#pragma unroll
        for (int j = 0; j < 16; j++) {
            float s = acc[r][j];
            s += __shfl_xor_sync(0xffffffffu, s, 16);
            s += __shfl_xor_sync(0xffffffffu, s, 8);
            s += __shfl_xor_sync(0xffffffffu, s, 4);
            s += __shfl_xor_sync(0xffffffffu, s, 2);
            s += __shfl_xor_sync(0xffffffffu, s, 1);
            acc[r][j] = s;
        }
        if (lid == 0) {
            float4* o = (float4*)(g_T + (size_t)(m0 + r) * 16);
            o[0] = make_float4(acc[r][0],  acc[r][1],  acc[r][2],  acc[r][3]);
            o[1] = make_float4(acc[r][4],  acc[r][5],  acc[r][6],  acc[r][7]);
            o[2] = make_float4(acc[r][8],  acc[r][9],  acc[r][10], acc[r][11]);
            o[3] = make_float4(acc[r][12], acc[r][13], acc[r][14], acc[r][15]);
        }
    }
}

// ---------------- main GEMM ----------------
// Quarter of the R13 load_chunk with IDENTICAL per-thread addressing:
// quarter Q = iteration i==Q of the original 4-iteration loop (2 cp.async/thread).
template <int Q>
__device__ __forceinline__ void load_chunk_quarter(char* stage, int m0, int n0, int chunk) {
    const int t = threadIdx.x;
    const int col0 = chunk * KC;
    uint32_t sA = smem_u32(stage);
    uint32_t sB = sA + TILE_B;
    int j   = t + Q * 256;          // 16B segment index within the 128x64 fp16 tile
    int row = j >> 3;
    int seg = j & 7;
    uint32_t off = (uint32_t)(row * ROW_B + seg * 16);
    cp_async16(sA + off, g_xh + (size_t)(m0 + row) * K_DIM + col0 + seg * 8);
    cp_async16(sB + off, g_wh + (size_t)(n0 + row) * K_DIM + col0 + seg * 8);
}
__device__ __forceinline__ void load_chunk(char* stage, int m0, int n0, int chunk) {
    load_chunk_quarter<0>(stage, m0, n0, chunk);
    load_chunk_quarter<1>(stage, m0, n0, chunk);
    load_chunk_quarter<2>(stage, m0, n0, chunk);
    load_chunk_quarter<3>(stage, m0, n0, chunk);
}

__global__ void __launch_bounds__(256, 2)
gemm_kernel(const float* __restrict__ bias,
            const float* __restrict__ Bq_pool,
            const float* __restrict__ Bv_pool,
            const int* __restrict__ idx,
            float* __restrict__ out) {
    extern __shared__ char smem[];
    const int tid = threadIdx.x;
    const int wid = tid >> 5;
    const int lid = tid & 31;
    const int wm  = wid & 1;       // 2 warps in M  (64 rows each)
    const int wn  = wid >> 1;      // 4 warps in N  (32 cols each)
    const int n0  = blockIdx.x * TN;
    const int m0  = blockIdx.y * TM;
    const int region = blockIdx.x >> 3;   // 0=q, 1=k, 2=v

    const int phase = ((blockIdx.x ^ blockIdx.y) & 1) * 8;
    const int ksoff = (wid >> 2) * 2;

    // ---- epilogue constants ----
    float* sh_bias = (float*)(smem + SM_BIAS);
    float* sh_B    = (float*)(smem + SM_EPB);
    if (tid < 128) sh_bias[tid] = bias[n0 + tid];
    const int pool_i = idx[blockIdx.y >> 5];   // 32 M-tiles (128 rows) per batch
    if (region != 1) {
        const float* Bp = (region == 0) ? (Bq_pool + (size_t)pool_i * POOL_RK * K_DIM)
                                        : (Bv_pool + (size_t)pool_i * POOL_RK * K_DIM);
        int colbase = (region == 0) ? n0 : (n0 - 2048);
#pragma unroll
        for (int e = tid; e < 1024; e += 256) {
            int r = e >> 7, c = e & 127;
            sh_B[e] = Bp[(size_t)r * K_DIM + colbase + c];
        }
    }

    // ---- accumulators ----
    float acc[4][4][4];
#pragma unroll
    for (int i = 0; i < 4; i++)
#pragma unroll
        for (int j = 0; j < 4; j++)
#pragma unroll
            for (int c = 0; c < 4; c++) acc[i][j][c] = 0.f;

    // per-thread ldmatrix source offsets
    const int a_row = (lid & 15);
    const int a_kh  = (lid >> 4) * 8;
    const int b_row = (lid & 7) + ((lid >> 4) << 3);
    const int b_kh  = ((lid >> 3) & 1) * 8;

    // ---- pipeline prologue: 2 stages in flight (one commit group per chunk) ----
    load_chunk(smem + SM_STAGE + 0 * STAGE_B, m0, n0, (0 + phase) & 15); CP_COMMIT();
    load_chunk(smem + SM_STAGE + 1 * STAGE_B, m0, n0, (1 + phase) & 15); CP_COMMIT();

    // ---- main K loop: one barrier per iteration ----
    for (int kc = 0; kc < NK; kc++) {
        if (kc == NK - 1) cp_wait<0>(); else cp_wait<1>();
        __syncthreads();
        // All warps are past compute of kc-1 => stage (kc+2)%3 (read at kc-1) is free.

        char* stage  = smem + SM_STAGE + (kc % NSTAGE) * STAGE_B;
        char* nstage = smem + SM_STAGE + ((kc + 2) % NSTAGE) * STAGE_B;
        const int kn  = kc + 2;
        const int knc = (kn + phase) & 15;
        uint32_t sA = smem_u32(stage);
        uint32_t sB = sA + TILE_B;
#pragma unroll
        for (int ks0 = 0; ks0 < 4; ks0++) {
            const int ks = (ks0 + ksoff) & 3;
            const int k0 = ks * 16;
            // B first (2 LDSM), then A[0] -> MMAs start after 3 LDSMs;
            // remaining A loads interleave with the MMA stream.
            uint32_t b[2][4];
#pragma unroll
            for (int g = 0; g < 2; g++) {
                uint32_t addr = sB + (uint32_t)((wn * 32 + g * 16 + b_row) * ROW_B
                                                + (k0 + b_kh) * 2);
                ldm_x4(b[g][0], b[g][1], b[g][2], b[g][3], addr);
            }
            uint32_t a[4][4];
            {
                uint32_t addr = sA + (uint32_t)((wm * 64 + 0 * 16 + a_row) * ROW_B
                                                + (k0 + a_kh) * 2);
                ldm_x4(a[0][0], a[0][1], a[0][2], a[0][3], addr);
            }
#pragma unroll
            for (int am = 0; am < 4; am++) {
                if (am < 3) {
                    uint32_t addr = sA + (uint32_t)((wm * 64 + (am + 1) * 16 + a_row) * ROW_B
                                                    + (k0 + a_kh) * 2);
                    ldm_x4(a[am + 1][0], a[am + 1][1], a[am + 1][2], a[am + 1][3], addr);
                }
#pragma unroll
                for (int an = 0; an < 4; an++) {
                    uint32_t bb[2] = { b[an >> 1][(an & 1) * 2],
                                       b[an >> 1][(an & 1) * 2 + 1] };
                    mma16816(acc[am][an], a[am], bb);
                }
            }
            // Deferred quarter refill with R13-identical addressing and commit
            // discipline: one quarter (2 cp.async/thread) per ks0, single commit
            // after the last. Exactly ONE commit group per chunk -> cp_wait<1>
            // semantics bit-identical to R13/R15; only issue placement changes.
            if (kn < NK) {
                if (ks0 == 0) { load_chunk_quarter<0>(nstage, m0, n0, knc); }
                if (ks0 == 1) { load_chunk_quarter<1>(nstage, m0, n0, knc); }
                if (ks0 == 2) { load_chunk_quarter<2>(nstage, m0, n0, knc); }
                if (ks0 == 3) { load_chunk_quarter<3>(nstage, m0, n0, knc); CP_COMMIT(); }
            }
        }
    }

    // ---- epilogue: bias + LoRA + store ----
    const bool lora = (region != 1);
    const int tq = lid >> 2;          // 0..7
    const int tr = lid & 3;           // 0..3
#pragma unroll
    for (int am = 0; am < 4; am++) {
#pragma unroll
        for (int h = 0; h < 2; h++) {
            const int lrow = wm * 64 + am * 16 + tq + h * 8;
            const size_t m = (size_t)(m0 + lrow);
            float t[8];
            if (lora) {
                const float* Tp = g_T + m * 16 + (region == 2 ? 8 : 0);
                float4 t0 = *(const float4*)Tp;
                float4 t1 = *(const float4*)(Tp + 4);
                t[0] = t0.x; t[1] = t0.y; t[2] = t0.z; t[3] = t0.w;
                t[4] = t1.x; t[5] = t1.y; t[6] = t1.z; t[7] = t1.w;
            }
#pragma unroll
            for (int an = 0; an < 4; an++) {
                const int lc = wn * 32 + an * 8 + tr * 2;
                float v0 = acc[am][an][h * 2 + 0] + sh_bias[lc];
                float v1 = acc[am][an][h * 2 + 1] + sh_bias[lc + 1];
                if (lora) {
#pragma unroll
                    for (int rr = 0; rr < 8; rr++) {
                        v0 += t[rr] * sh_B[rr * 128 + lc];
                        v1 += t[rr] * sh_B[rr * 128 + lc + 1];
                    }
                }
                *(float2*)(out + m * N_DIM + n0 + lc) = make_float2(v0, v1);
            }
        }
    }
}

// ---------------- launch ----------------
extern "C" void kernel_launch(void* const* d_in, const int* in_sizes, int n_in,
                              void* d_out, int out_size) {
    (void)in_sizes; (void)n_in; (void)out_size;
    const float* x    = (const float*)d_in[0];
    const float* w    = (const float*)d_in[1];
    const float* bias = (const float*)d_in[2];
    const float* Aq   = (const float*)d_in[3];
    const float* Bq   = (const float*)d_in[4];
    const float* Av   = (const float*)d_in[5];
    const float* Bv   = (const float*)d_in[6];
    const int*   idx  = (const int*)d_in[7];
    float* out = (float*)d_out;

    static bool attr_set = false;
    if (!attr_set) {
        cudaFuncSetAttribute(gemm_kernel, cudaFuncAttributeMaxDynamicSharedMemorySize,
                             SM_TOTAL);
        cudaFuncSetAttribute(cvt_lora_kernel, cudaFuncAttributeMaxDynamicSharedMemorySize,
                             LORA_SMEM);
        attr_set = true;
    }

    const size_t w4 = (size_t)N_DIM * K_DIM / 4;
    cvt_w_kernel<<<(unsigned)((w4 + 255) / 256), 256>>>(w);
    cvt_lora_kernel<<<M_TOT / 32, 256, LORA_SMEM>>>(x, Aq, Av, idx);

    dim3 grid(N_DIM / TN, M_TOT / TM, 1);
    gemm_kernel<<<grid, 256, SM_TOTAL>>>(bias, Bq, Bv, idx, out);
}